// round 5
// baseline (speedup 1.0000x reference)
#include <cuda_runtime.h>
#include <cuda_bf16.h>
#include <cstdint>

#define Nn 16384
#define Dd 64
#define KK 17
#define Ee (Nn*16)
#define Ll 4

typedef unsigned long long ull;

// ---------------- scratch (static device allocations) ----------------
__device__ float g_h[Nn*Dd];
__device__ float g_hsq[Nn];                     // 0.5 * ||h_i||^2 (from splits)
__device__ int   g_idx[Nn*KK];
__device__ float g_y1[(size_t)Ee*Dd];
__device__ float g_y2[(size_t)Ee*Dd];
__device__ float g_agg[Nn*Dd];
__device__ float g_u1[Nn*Dd];
__device__ float g_u2[Nn*Dd];
__device__ float g_part[2048*128];
__device__ float g_scale[Dd];
__device__ float g_shift[Dd];
// pre-SW128-swizzled bf16 splits of h (row = node, 128 bytes/row)
__device__ unsigned g_hb_hi[Nn*32];
__device__ unsigned g_hb_lo[Nn*32];

// ---------------- packed f32x2 helpers (for MLP GEMMs) ----------------
__device__ __forceinline__ ull ff2(ull a, ull b, ull c) {
    ull d;
    asm("fma.rn.f32x2 %0, %1, %2, %3;" : "=l"(d) : "l"(a), "l"(b), "l"(c));
    return d;
}
__device__ __forceinline__ ull dup2(float x) {
    ull d;
    unsigned u = __float_as_uint(x);
    asm("mov.b64 %0, {%1, %1};" : "=l"(d) : "r"(u));
    return d;
}
__device__ __forceinline__ float2 up2(ull v) {
    float2 r;
    asm("mov.b64 {%0, %1}, %2;" : "=f"(r.x), "=f"(r.y) : "l"(v));
    return r;
}

// ---------------- sm_80-era async-copy / ldmatrix / mma helpers --------
__device__ __forceinline__ uint32_t smem_u32(const void* p) {
    uint32_t a;
    asm("{ .reg .u64 t; cvta.to.shared.u64 t, %1; cvt.u32.u64 %0, t; }"
        : "=r"(a) : "l"(p));
    return a;
}
__device__ __forceinline__ void cp16(uint32_t d, const void* s) {
    asm volatile("cp.async.cg.shared.global [%0], [%1], 16;"
                 :: "r"(d), "l"(s) : "memory");
}
__device__ __forceinline__ void cp_commit() {
    asm volatile("cp.async.commit_group;" ::: "memory");
}
template<int N> __device__ __forceinline__ void cp_wait() {
    asm volatile("cp.async.wait_group %0;" :: "n"(N) : "memory");
}
__device__ __forceinline__ void ldsm4(uint32_t& r0, uint32_t& r1,
                                      uint32_t& r2, uint32_t& r3, uint32_t a) {
    asm volatile("ldmatrix.sync.aligned.m8n8.x4.shared.b16 {%0,%1,%2,%3}, [%4];"
                 : "=r"(r0), "=r"(r1), "=r"(r2), "=r"(r3) : "r"(a));
}
__device__ __forceinline__ void mma_bf16(float& c0, float& c1, float& c2, float& c3,
                                         uint32_t a0, uint32_t a1, uint32_t a2,
                                         uint32_t a3, uint32_t b0, uint32_t b1) {
    asm volatile(
        "mma.sync.aligned.m16n8k16.row.col.f32.bf16.bf16.f32 "
        "{%0,%1,%2,%3}, {%4,%5,%6,%7}, {%8,%9}, {%0,%1,%2,%3};"
        : "+f"(c0), "+f"(c1), "+f"(c2), "+f"(c3)
        : "r"(a0), "r"(a1), "r"(a2), "r"(a3), "r"(b0), "r"(b1));
}
__device__ __forceinline__ uint32_t sw128(uint32_t off) {
    return off ^ ((off >> 3) & 0x70u);
}

// ---------------- input projection ----------------
__global__ void k_lin_in(const float* __restrict__ pos,
                         const float* __restrict__ W,
                         const float* __restrict__ b) {
    __shared__ float sW[11*64];
    __shared__ float sp[11];
    const int i = blockIdx.x;
    const int f = threadIdx.x;
    for (int t = f; t < 11*64; t += 64) sW[t] = W[t];
    if (f < 11) sp[f] = pos[i*11 + f];
    __syncthreads();
    float acc = b[f];
    #pragma unroll
    for (int c = 0; c < 11; c++) acc = fmaf(sp[c], sW[c*64 + f], acc);
    g_h[i*64 + f] = acc;
}

// ---------------- 2-way bf16 split + swizzled store + 0.5*sq ----------
__global__ void k_split() {
    const int node = blockIdx.x*8 + (threadIdx.x >> 5);
    const int lane = threadIdx.x & 31;
    float2 f = *(const float2*)(g_h + (size_t)node*64 + lane*2);

    __nv_bfloat16 h0 = __float2bfloat16(f.x);
    __nv_bfloat16 l0 = __float2bfloat16(f.x - __bfloat162float(h0));
    __nv_bfloat16 h1 = __float2bfloat16(f.y);
    __nv_bfloat16 l1 = __float2bfloat16(f.y - __bfloat162float(h1));
    float a0 = __bfloat162float(h0) + __bfloat162float(l0);
    float a1 = __bfloat162float(h1) + __bfloat162float(l1);

    unsigned off = (unsigned)node*128u + (unsigned)lane*4u;
    unsigned sw  = sw128(off);
    *(unsigned*)((char*)g_hb_hi + sw) =
        (unsigned)__bfloat16_as_ushort(h0) | ((unsigned)__bfloat16_as_ushort(h1) << 16);
    *(unsigned*)((char*)g_hb_lo + sw) =
        (unsigned)__bfloat16_as_ushort(l0) | ((unsigned)__bfloat16_as_ushort(l1) << 16);

    float s = a0*a0 + a1*a1;
    #pragma unroll
    for (int o = 16; o > 0; o >>= 1) s += __shfl_down_sync(0xffffffffu, s, o);
    if (lane == 0) g_hsq[node] = 0.5f * s;
}

// ---------------- fused mma.sync d2 + top-17 ----------------
#define OB_B    0u
#define OB_A    65536u
#define OB_HSQ  98304u
#define OB_LV   99328u
#define OB_LI   108032u
#define SMEM_D2 (116736u + 1024u)

__device__ __forceinline__ void ins17(float* lv, int* li, float v, int j) {
    int p = 16;
    while (p > 0 && lv[p-1] > v) { lv[p] = lv[p-1]; li[p] = li[p-1]; p--; }
    lv[p] = v; li[p] = j;
}

__global__ __launch_bounds__(256) void k_d2topk() {
    extern __shared__ __align__(16) char smraw[];
    const uint32_t rawb = smem_u32(smraw);
    const uint32_t sb = (rawb + 1023u) & ~1023u;
    char* smc = smraw + (sb - rawb);

    const int tid  = threadIdx.x;
    const int w    = tid >> 5;
    const int lane = tid & 31;
    const int row0 = blockIdx.x * 128;

    float* lv = (float*)(smc + OB_LV);
    int*   li = (int*)  (smc + OB_LI);

    // ---- prologue: async copies (A, B0, B1) ----
    {
        const char* srchi = (const char*)g_hb_hi + (size_t)row0*128;
        const char* srclo = (const char*)g_hb_lo + (size_t)row0*128;
        for (int i = tid; i < 1024; i += 256) {
            cp16(sb + OB_A + i*16,          srchi + i*16);
            cp16(sb + OB_A + 16384 + i*16,  srclo + i*16);
        }
        cp_commit();
        #pragma unroll
        for (int tt = 0; tt < 2; tt++) {
            const char* bhi = (const char*)g_hb_hi + (size_t)tt*16384;
            const char* blo = (const char*)g_hb_lo + (size_t)tt*16384;
            uint32_t dst = sb + OB_B + (uint32_t)tt*32768u;
            for (int i = tid; i < 1024; i += 256) {
                cp16(dst + i*16,          bhi + i*16);
                cp16(dst + 16384 + i*16,  blo + i*16);
            }
            if (tid < 32) cp16(sb + OB_HSQ + (uint32_t)tt*512u + tid*16,
                               (const char*)g_hsq + (size_t)tt*512 + tid*16);
            cp_commit();
        }
    }
    if (tid < 128) {
        #pragma unroll
        for (int p = 0; p < 17; p++) {
            lv[tid*17 + p] = 3.4e38f;
            li[tid*17 + p] = 0x7FFFFFFF;
        }
    }
    cp_wait<1>();          // A + B0 resident
    __syncthreads();

    // ---- preload A fragments (fixed across all tiles) ----
    uint32_t af[2][4][4];
    {
        const int m  = lane >> 3;
        const int rr = (w << 4) + ((m & 1) << 3) + (lane & 7);
        const int kb0 = (m >> 1) << 4;
        #pragma unroll
        for (int sp = 0; sp < 2; sp++) {
            uint32_t base = sb + OB_A + (uint32_t)sp*16384u;
            #pragma unroll
            for (int ks = 0; ks < 4; ks++) {
                uint32_t loc = (uint32_t)rr*128u + (uint32_t)(ks*32 + kb0);
                ldsm4(af[sp][ks][0], af[sp][ks][1], af[sp][ks][2], af[sp][ks][3],
                      base + sw128(loc));
            }
        }
    }

    const int q   = lane >> 2;            // row within m16 (and +8)
    const int s3  = lane & 3;             // column pair selector
    const int lr0 = (w << 4) + q;
    const int lr1 = lr0 + 8;
    float th0 = 3.4e38f, th1 = 3.4e38f;

    const int bm = lane >> 3;             // ldmatrix B address helper
    const int bn = lane & 7;

    for (int t = 0; t < 128; t++) {
        const uint32_t bbase = sb + OB_B + (uint32_t)(t & 1)*32768u;
        const char* hsqp = smc + OB_HSQ + (uint32_t)(t & 1)*512u;
        const int jb = t * 128;

        #pragma unroll 2
        for (int nb = 0; nb < 16; nb++) {
            // ---- B fragments: 2 splits x 4 k-steps via 4 ldmatrix.x4 ----
            uint32_t bh[8], bl[8];
            {
                uint32_t loc = (uint32_t)((nb*8 + bn)*128 + bm*16);
                ldsm4(bh[0], bh[1], bh[2], bh[3], bbase + sw128(loc));
                ldsm4(bh[4], bh[5], bh[6], bh[7], bbase + sw128(loc + 64u));
                uint32_t lb = bbase + 16384u;
                ldsm4(bl[0], bl[1], bl[2], bl[3], lb + sw128(loc));
                ldsm4(bl[4], bl[5], bl[6], bl[7], lb + sw128(loc + 64u));
            }
            // ---- 3 independent accumulator chains: hi*hi, hi*lo, lo*hi ----
            float h0 = 0.f, h1 = 0.f, h2 = 0.f, h3 = 0.f;   // hi*hi
            float m0 = 0.f, m1 = 0.f, m2 = 0.f, m3 = 0.f;   // hi*lo
            float g0 = 0.f, g1 = 0.f, g2 = 0.f, g3 = 0.f;   // lo*hi
            #pragma unroll
            for (int ks = 0; ks < 4; ks++) {
                mma_bf16(h0, h1, h2, h3,
                         af[0][ks][0], af[0][ks][1], af[0][ks][2], af[0][ks][3],
                         bh[2*ks], bh[2*ks+1]);
                mma_bf16(m0, m1, m2, m3,
                         af[0][ks][0], af[0][ks][1], af[0][ks][2], af[0][ks][3],
                         bl[2*ks], bl[2*ks+1]);
                mma_bf16(g0, g1, g2, g3,
                         af[1][ks][0], af[1][ks][1], af[1][ks][2], af[1][ks][3],
                         bh[2*ks], bh[2*ks+1]);
            }
            float c0 = h0 + m0 + g0;
            float c1 = h1 + m1 + g1;
            float c2 = h2 + m2 + g2;
            float c3 = h3 + m3 + g3;

            // ---- epilogue: key = 0.5*sq_c - dot; threshold + rare insert ----
            float2 hs = *(const float2*)(hsqp + (nb*8 + 2*s3)*4);
            float k0 = hs.x - c0;
            float k1 = hs.y - c1;
            float k2 = hs.x - c2;
            float k3 = hs.y - c3;
            bool p0 = k0 < th0, p1 = k1 < th0, p2 = k2 < th1, p3 = k3 < th1;
            unsigned need = __ballot_sync(0xffffffffu, p0 | p1 | p2 | p3);
            if (need) {
                const int colb = jb + nb*8 + 2*s3;
                #pragma unroll
                for (int s = 0; s < 4; s++) {
                    if (need & (0x11111111u << s)) {
                        __syncwarp();
                        if (s3 == s) {
                            if (p0 | p1) {
                                float* L0 = lv + lr0*17; int* I0 = li + lr0*17;
                                float t0 = L0[16];
                                if (k0 < t0) { ins17(L0, I0, k0, colb);   t0 = L0[16]; }
                                if (k1 < t0) { ins17(L0, I0, k1, colb+1); }
                            }
                            if (p2 | p3) {
                                float* L1 = lv + lr1*17; int* I1 = li + lr1*17;
                                float t1 = L1[16];
                                if (k2 < t1) { ins17(L1, I1, k2, colb);   t1 = L1[16]; }
                                if (k3 < t1) { ins17(L1, I1, k3, colb+1); }
                            }
                        }
                    }
                }
                __syncwarp();
                th0 = lv[lr0*17 + 16];
                th1 = lv[lr1*17 + 16];
            }
        }

        __syncthreads();     // all warps done with buf[t&1] + lists stable
        if (t + 2 < 128) {
            const int tt = t + 2;
            const char* bhi = (const char*)g_hb_hi + (size_t)tt*16384;
            const char* blo = (const char*)g_hb_lo + (size_t)tt*16384;
            uint32_t dst = sb + OB_B + (uint32_t)(t & 1)*32768u;
            for (int i = tid; i < 1024; i += 256) {
                cp16(dst + i*16,          bhi + i*16);
                cp16(dst + 16384 + i*16,  blo + i*16);
            }
            if (tid < 32) cp16(sb + OB_HSQ + (uint32_t)(t & 1)*512u + tid*16,
                               (const char*)g_hsq + (size_t)tt*512 + tid*16);
            cp_commit();
            cp_wait<1>();    // tile t+1 resident
        } else {
            cp_wait<0>();
        }
        __syncthreads();
    }

    if (tid < 128) {
        #pragma unroll
        for (int p = 0; p < 17; p++)
            g_idx[(row0 + tid)*KK + p] = li[tid*17 + p];
    }
}

// ------------- GEMM A: depth-128 (MODE 0: msg gather, MODE 1: upd concat)
template<int MODE>
__global__ __launch_bounds__(256) void k_gemm_a(const float* __restrict__ W,
                                                const float* __restrict__ bias) {
    __shared__ float As[64][128];
    __shared__ float Ws[64][64];
    const int tid = threadIdx.x;
    const int e0  = blockIdx.x * 128;
    const int r0  = (tid >> 4) * 8;
    const int f0  = (tid & 15) * 4;
    ull acc[4][4];
    #pragma unroll
    for (int rp = 0; rp < 4; rp++)
        #pragma unroll
        for (int c = 0; c < 4; c++) acc[rp][c] = 0ull;

    for (int p = 0; p < 2; p++) {
        for (int t = tid; t < 1024; t += 256) {
            int f4 = t & 15, kk = t >> 4;
            *(float4*)&Ws[kk][f4<<2] =
                *(const float4*)(W + (size_t)((p<<6)+kk)*64 + (f4<<2));
        }
        for (int t = tid; t < 2048; t += 256) {
            int e = t & 127, k4 = t >> 7;
            int eg = e0 + e;
            const float* src;
            if (MODE == 0) {
                int i = eg & (Nn-1);
                int node = (p == 0) ? g_idx[i*KK + 1 + (eg >> 14)] : g_idx[i*KK];
                src = g_h + (size_t)node*64;
            } else {
                src = (p == 0 ? g_h : g_agg) + (size_t)eg*64;
            }
            float4 v = *(const float4*)(src + (k4<<2));
            As[(k4<<2)+0][e] = v.x; As[(k4<<2)+1][e] = v.y;
            As[(k4<<2)+2][e] = v.z; As[(k4<<2)+3][e] = v.w;
        }
        __syncthreads();
        #pragma unroll 4
        for (int k = 0; k < 64; k++) {
            ulonglong2 a01 = *(const ulonglong2*)(&As[k][r0]);
            ulonglong2 a23 = *(const ulonglong2*)(&As[k][r0+4]);
            float4 b = *(const float4*)(&Ws[k][f0]);
            ull ar[4] = { a01.x, a01.y, a23.x, a23.y };
            ull bd[4] = { dup2(b.x), dup2(b.y), dup2(b.z), dup2(b.w) };
            #pragma unroll
            for (int rp = 0; rp < 4; rp++)
                #pragma unroll
                for (int c = 0; c < 4; c++)
                    acc[rp][c] = ff2(ar[rp], bd[c], acc[rp][c]);
        }
        __syncthreads();
    }

    float* out = (MODE == 0) ? g_y1 : g_u1;
    float4 bv = *(const float4*)(bias + f0);
    #pragma unroll
    for (int rp = 0; rp < 4; rp++) {
        float2 u0 = up2(acc[rp][0]), u1 = up2(acc[rp][1]);
        float2 u2 = up2(acc[rp][2]), u3 = up2(acc[rp][3]);
        int ea = e0 + r0 + 2*rp;
        *(float4*)(out + (size_t)ea*64 + f0) =
            make_float4(u0.x + bv.x, u1.x + bv.y, u2.x + bv.z, u3.x + bv.w);
        *(float4*)(out + (size_t)(ea+1)*64 + f0) =
            make_float4(u0.y + bv.x, u1.y + bv.y, u2.y + bv.z, u3.y + bv.w);
    }
}

// ------------- GEMM B: depth-64 with fused BN-affine + ReLU on input ----
template<int MODE>
__global__ __launch_bounds__(256) void k_gemm_b(const float* __restrict__ W,
                                                const float* __restrict__ bias) {
    __shared__ float As[64][128];
    __shared__ float Ws[64][64];
    const int tid = threadIdx.x;
    const int e0  = blockIdx.x * 128;
    const int r0  = (tid >> 4) * 8;
    const int f0  = (tid & 15) * 4;

    const float* in = (MODE == 0) ? g_y1 : g_u1;

    for (int t = tid; t < 1024; t += 256) {
        int f4 = t & 15, kk = t >> 4;
        *(float4*)&Ws[kk][f4<<2] = *(const float4*)(W + (size_t)kk*64 + (f4<<2));
    }
    for (int t = tid; t < 2048; t += 256) {
        int e = t & 127, k4 = t >> 7;
        int eg = e0 + e;
        float4 v  = *(const float4*)(in + (size_t)eg*64 + (k4<<2));
        float4 sc = *(const float4*)(g_scale + (k4<<2));
        float4 sh = *(const float4*)(g_shift + (k4<<2));
        As[(k4<<2)+0][e] = fmaxf(fmaf(v.x, sc.x, sh.x), 0.f);
        As[(k4<<2)+1][e] = fmaxf(fmaf(v.y, sc.y, sh.y), 0.f);
        As[(k4<<2)+2][e] = fmaxf(fmaf(v.z, sc.z, sh.z), 0.f);
        As[(k4<<2)+3][e] = fmaxf(fmaf(v.w, sc.w, sh.w), 0.f);
    }
    __syncthreads();

    ull acc[4][4];
    #pragma unroll
    for (int rp = 0; rp < 4; rp++)
        #pragma unroll
        for (int c = 0; c < 4; c++) acc[rp][c] = 0ull;

    #pragma unroll 4
    for (int k = 0; k < 64; k++) {
        ulonglong2 a01 = *(const ulonglong2*)(&As[k][r0]);
        ulonglong2 a23 = *(const ulonglong2*)(&As[k][r0+4]);
        float4 b = *(const float4*)(&Ws[k][f0]);
        ull ar[4] = { a01.x, a01.y, a23.x, a23.y };
        ull bd[4] = { dup2(b.x), dup2(b.y), dup2(b.z), dup2(b.w) };
        #pragma unroll
        for (int rp = 0; rp < 4; rp++)
            #pragma unroll
            for (int c = 0; c < 4; c++)
                acc[rp][c] = ff2(ar[rp], bd[c], acc[rp][c]);
    }

    float* out = (MODE == 0) ? g_y2 : g_u2;
    float4 bv = *(const float4*)(bias + f0);
    #pragma unroll
    for (int rp = 0; rp < 4; rp++) {
        float2 u0 = up2(acc[rp][0]), u1 = up2(acc[rp][1]);
        float2 u2 = up2(acc[rp][2]), u3 = up2(acc[rp][3]);
        int ea = e0 + r0 + 2*rp;
        *(float4*)(out + (size_t)ea*64 + f0) =
            make_float4(u0.x + bv.x, u1.x + bv.y, u2.x + bv.z, u3.x + bv.w);
        *(float4*)(out + (size_t)(ea+1)*64 + f0) =
            make_float4(u0.y + bv.x, u1.y + bv.y, u2.y + bv.z, u3.y + bv.w);
    }
}

// ---------------- batch statistics (deterministic two-pass) ------------
__device__ __forceinline__ const float* stat_src(int sel) {
    switch (sel) {
        case 0: return g_y1;
        case 1: return g_y2;
        case 2: return g_u1;
        case 3: return g_u2;
        default: return g_h;
    }
}

__global__ void k_stats(int sel, int M, int P) {
    const float* __restrict__ x = stat_src(sel);
    const int t = threadIdx.x;
    float s = 0.f, s2 = 0.f;
    const size_t total = (size_t)M * 64;
    for (size_t idx = (size_t)blockIdx.x*256 + t; idx < total; idx += (size_t)P*256) {
        float v = x[idx];
        s += v; s2 = fmaf(v, v, s2);
    }
    __shared__ float sh[256], sh2[256];
    sh[t] = s; sh2[t] = s2;
    __syncthreads();
    if (t < 64) {
        s  = sh[t]  + sh[t+64]  + sh[t+128]  + sh[t+192];
        s2 = sh2[t] + sh2[t+64] + sh2[t+128] + sh2[t+192];
        g_part[(size_t)blockIdx.x*128 + t]      = s;
        g_part[(size_t)blockIdx.x*128 + 64 + t] = s2;
    }
}

__global__ void k_stats_fin(int M, int P,
                            const float* __restrict__ g,
                            const float* __restrict__ be) {
    const int f = threadIdx.x;
    float s = 0.f, s2 = 0.f;
    for (int p = 0; p < P; p++) {
        s  += g_part[(size_t)p*128 + f];
        s2 += g_part[(size_t)p*128 + 64 + f];
    }
    const float inv  = 1.f / (float)M;
    const float mean = s * inv;
    const float var  = fmaf(-mean, mean, s2 * inv);
    const float sc   = g[f] * rsqrtf(var + 1e-5f);
    g_scale[f] = sc;
    g_shift[f] = fmaf(-mean, sc, be[f]);
}

// ---------------- zero, scatter, residual ----------------
__global__ void k_zero_agg() {
    int i = blockIdx.x*blockDim.x + threadIdx.x;
    g_agg[i] = 0.f;
}

__global__ void k_scatter() {
    const int gid = blockIdx.x*256 + threadIdx.x;
    const int q = gid & 15;
    const int e = gid >> 4;
    const int i = e & (Nn-1);
    const int to = g_idx[i*KK + 1 + (e >> 14)];
    const int f = q << 2;
    float4 v  = *(const float4*)(g_y2 + (size_t)e*64 + f);
    float4 sc = *(const float4*)(g_scale + f);
    float4 sh = *(const float4*)(g_shift + f);
    float* dst = g_agg + (size_t)to*64 + f;
    atomicAdd(dst+0, fmaxf(fmaf(v.x, sc.x, sh.x), 0.f));
    atomicAdd(dst+1, fmaxf(fmaf(v.y, sc.y, sh.y), 0.f));
    atomicAdd(dst+2, fmaxf(fmaf(v.z, sc.z, sh.z), 0.f));
    atomicAdd(dst+3, fmaxf(fmaf(v.w, sc.w, sh.w), 0.f));
}

__global__ void k_resid() {
    const int gid = blockIdx.x*blockDim.x + threadIdx.x;
    const int f = gid & 63;
    const float v = g_u2[gid];
    g_h[gid] += fmaxf(fmaf(v, g_scale[f], g_shift[f]), 0.f);
}

// ---------------- final pool + prediction ----------------
__global__ void k_fin(const float* __restrict__ pW,
                      const float* __restrict__ pb,
                      float* __restrict__ out, int P) {
    const int f = threadIdx.x;
    float s = 0.f;
    for (int p = 0; p < P; p++) s += g_part[(size_t)p*128 + f];
    float v = (s / (float)Nn) * pW[f];
    __shared__ float red[64];
    red[f] = v;
    __syncthreads();
    if (f < 32) {
        float x = red[f] + red[f+32];
        #pragma unroll
        for (int o = 16; o > 0; o >>= 1) x += __shfl_down_sync(0xffffffffu, x, o);
        if (f == 0) out[0] = x + pb[0];
    }
}

// ---------------- host driver ----------------
extern "C" void kernel_launch(void* const* d_in, const int* in_sizes, int n_in,
                              void* d_out, int out_size) {
    const float* pos    = (const float*)d_in[0];
    const float* linW   = (const float*)d_in[1];
    const float* linb   = (const float*)d_in[2];
    const float* predW  = (const float*)d_in[3];
    const float* predb  = (const float*)d_in[4];
    const float* msgW1  = (const float*)d_in[5];
    const float* msgb1  = (const float*)d_in[6];
    const float* msgg1  = (const float*)d_in[7];
    const float* msgbe1 = (const float*)d_in[8];
    const float* msgW2  = (const float*)d_in[9];
    const float* msgb2  = (const float*)d_in[10];
    const float* msgg2  = (const float*)d_in[11];
    const float* msgbe2 = (const float*)d_in[12];
    const float* updW1  = (const float*)d_in[13];
    const float* updb1  = (const float*)d_in[14];
    const float* updg1  = (const float*)d_in[15];
    const float* updbe1 = (const float*)d_in[16];
    const float* updW2  = (const float*)d_in[17];
    const float* updb2  = (const float*)d_in[18];
    const float* updg2  = (const float*)d_in[19];
    const float* updbe2 = (const float*)d_in[20];
    float* out = (float*)d_out;

    static int smem_set = 0;
    if (!smem_set) {
        cudaFuncSetAttribute(k_d2topk, cudaFuncAttributeMaxDynamicSharedMemorySize,
                             SMEM_D2);
        smem_set = 1;
    }

    k_lin_in<<<Nn, 64>>>(pos, linW, linb);

    for (int l = 0; l < Ll; l++) {
        // ---- KNN: bf16 split + mma.sync d2 + top-17 ----
        k_split<<<Nn/8, 256>>>();
        k_d2topk<<<Nn/128, 256, SMEM_D2>>>();

        // ---- message MLP over E edges ----
        k_gemm_a<0><<<Ee/128, 256>>>(msgW1 + (size_t)l*128*64, msgb1 + l*64);
        k_stats<<<2048, 256>>>(0, Ee, 2048);
        k_stats_fin<<<1, 64>>>(Ee, 2048, msgg1 + l*64, msgbe1 + l*64);
        k_gemm_b<0><<<Ee/128, 256>>>(msgW2 + (size_t)l*64*64, msgb2 + l*64);
        k_stats<<<2048, 256>>>(1, Ee, 2048);
        k_stats_fin<<<1, 64>>>(Ee, 2048, msgg2 + l*64, msgbe2 + l*64);

        // ---- aggregate ----
        k_zero_agg<<<Nn*64/256, 256>>>();
        k_scatter<<<Ee*16/256, 256>>>();

        // ---- update MLP + residual ----
        k_gemm_a<1><<<Nn/128, 256>>>(updW1 + (size_t)l*128*64, updb1 + l*64);
        k_stats<<<64, 256>>>(2, Nn, 64);
        k_stats_fin<<<1, 64>>>(Nn, 64, updg1 + l*64, updbe1 + l*64);
        k_gemm_b<1><<<Nn/128, 256>>>(updW2 + (size_t)l*64*64, updb2 + l*64);
        k_stats<<<64, 256>>>(3, Nn, 64);
        k_stats_fin<<<1, 64>>>(Nn, 64, updg2 + l*64, updbe2 + l*64);
        k_resid<<<Nn*64/256, 256>>>();
    }

    k_stats<<<64, 256>>>(4, Nn, 64);
    k_fin<<<1, 64>>>(predW, predb, out, 64);
}

// round 6
// speedup vs baseline: 1.5070x; 1.5070x over previous
#include <cuda_runtime.h>
#include <cuda_bf16.h>
#include <cstdint>

#define Nn 16384
#define Dd 64
#define KK 17
#define Ee (Nn*16)
#define Ll 4

typedef unsigned long long ull;

// ---------------- scratch (static device allocations) ----------------
__device__ float g_h[Nn*Dd];
__device__ float g_hsq[Nn];                     // 0.5 * ||h_i||^2 (from splits)
__device__ int   g_idx[Nn*KK];
__device__ float g_y1[(size_t)Ee*Dd];
__device__ float g_y2[(size_t)Ee*Dd];
__device__ float g_agg[Nn*Dd];
__device__ float g_u1[Nn*Dd];
__device__ float g_u2[Nn*Dd];
__device__ float g_part[2048*128];
__device__ float g_scale[Dd];
__device__ float g_shift[Dd];
// pre-SW128-swizzled bf16 splits of h (row = node, 128 bytes/row)
__device__ unsigned g_hb_hi[Nn*32];
__device__ unsigned g_hb_lo[Nn*32];

// ---------------- packed f32x2 helpers (for MLP GEMMs) ----------------
__device__ __forceinline__ ull ff2(ull a, ull b, ull c) {
    ull d;
    asm("fma.rn.f32x2 %0, %1, %2, %3;" : "=l"(d) : "l"(a), "l"(b), "l"(c));
    return d;
}
__device__ __forceinline__ ull dup2(float x) {
    ull d;
    unsigned u = __float_as_uint(x);
    asm("mov.b64 %0, {%1, %1};" : "=l"(d) : "r"(u));
    return d;
}
__device__ __forceinline__ float2 up2(ull v) {
    float2 r;
    asm("mov.b64 {%0, %1}, %2;" : "=f"(r.x), "=f"(r.y) : "l"(v));
    return r;
}

// ---------------- sm_80-era async-copy / ldmatrix / mma helpers --------
__device__ __forceinline__ uint32_t smem_u32(const void* p) {
    uint32_t a;
    asm("{ .reg .u64 t; cvta.to.shared.u64 t, %1; cvt.u32.u64 %0, t; }"
        : "=r"(a) : "l"(p));
    return a;
}
__device__ __forceinline__ void cp16(uint32_t d, const void* s) {
    asm volatile("cp.async.cg.shared.global [%0], [%1], 16;"
                 :: "r"(d), "l"(s) : "memory");
}
__device__ __forceinline__ void cp_commit() {
    asm volatile("cp.async.commit_group;" ::: "memory");
}
template<int N> __device__ __forceinline__ void cp_wait() {
    asm volatile("cp.async.wait_group %0;" :: "n"(N) : "memory");
}
__device__ __forceinline__ void ldsm4(uint32_t& r0, uint32_t& r1,
                                      uint32_t& r2, uint32_t& r3, uint32_t a) {
    asm volatile("ldmatrix.sync.aligned.m8n8.x4.shared.b16 {%0,%1,%2,%3}, [%4];"
                 : "=r"(r0), "=r"(r1), "=r"(r2), "=r"(r3) : "r"(a));
}
__device__ __forceinline__ void mma_bf16(float& c0, float& c1, float& c2, float& c3,
                                         uint32_t a0, uint32_t a1, uint32_t a2,
                                         uint32_t a3, uint32_t b0, uint32_t b1) {
    asm volatile(
        "mma.sync.aligned.m16n8k16.row.col.f32.bf16.bf16.f32 "
        "{%0,%1,%2,%3}, {%4,%5,%6,%7}, {%8,%9}, {%0,%1,%2,%3};"
        : "+f"(c0), "+f"(c1), "+f"(c2), "+f"(c3)
        : "r"(a0), "r"(a1), "r"(a2), "r"(a3), "r"(b0), "r"(b1));
}
__device__ __forceinline__ uint32_t sw128(uint32_t off) {
    return off ^ ((off >> 3) & 0x70u);
}

// ---------------- input projection ----------------
__global__ void k_lin_in(const float* __restrict__ pos,
                         const float* __restrict__ W,
                         const float* __restrict__ b) {
    __shared__ float sW[11*64];
    __shared__ float sp[11];
    const int i = blockIdx.x;
    const int f = threadIdx.x;
    for (int t = f; t < 11*64; t += 64) sW[t] = W[t];
    if (f < 11) sp[f] = pos[i*11 + f];
    __syncthreads();
    float acc = b[f];
    #pragma unroll
    for (int c = 0; c < 11; c++) acc = fmaf(sp[c], sW[c*64 + f], acc);
    g_h[i*64 + f] = acc;
}

// ---------------- 2-way bf16 split + swizzled store + 0.5*sq ----------
__global__ void k_split() {
    const int node = blockIdx.x*8 + (threadIdx.x >> 5);
    const int lane = threadIdx.x & 31;
    float2 f = *(const float2*)(g_h + (size_t)node*64 + lane*2);

    __nv_bfloat16 h0 = __float2bfloat16(f.x);
    __nv_bfloat16 l0 = __float2bfloat16(f.x - __bfloat162float(h0));
    __nv_bfloat16 h1 = __float2bfloat16(f.y);
    __nv_bfloat16 l1 = __float2bfloat16(f.y - __bfloat162float(h1));
    float a0 = __bfloat162float(h0) + __bfloat162float(l0);
    float a1 = __bfloat162float(h1) + __bfloat162float(l1);

    unsigned off = (unsigned)node*128u + (unsigned)lane*4u;
    unsigned sw  = sw128(off);
    *(unsigned*)((char*)g_hb_hi + sw) =
        (unsigned)__bfloat16_as_ushort(h0) | ((unsigned)__bfloat16_as_ushort(h1) << 16);
    *(unsigned*)((char*)g_hb_lo + sw) =
        (unsigned)__bfloat16_as_ushort(l0) | ((unsigned)__bfloat16_as_ushort(l1) << 16);

    float s = a0*a0 + a1*a1;
    #pragma unroll
    for (int o = 16; o > 0; o >>= 1) s += __shfl_down_sync(0xffffffffu, s, o);
    if (lane == 0) g_hsq[node] = 0.5f * s;
}

// ---------------- fused mma.sync d2 + top-17 ----------------
#define OB_B    0u
#define OB_A    65536u
#define OB_HSQ  98304u
#define OB_LV   99328u
#define OB_LI   108032u
#define SMEM_D2 (116736u + 1024u)

__device__ __forceinline__ void ins17(float* lv, int* li, float v, int j) {
    int p = 16;
    while (p > 0 && lv[p-1] > v) { lv[p] = lv[p-1]; li[p] = li[p-1]; p--; }
    lv[p] = v; li[p] = j;
}

__global__ __launch_bounds__(256) void k_d2topk() {
    extern __shared__ __align__(16) char smraw[];
    const uint32_t rawb = smem_u32(smraw);
    const uint32_t sb = (rawb + 1023u) & ~1023u;
    char* smc = smraw + (sb - rawb);

    const int tid  = threadIdx.x;
    const int w    = tid >> 5;
    const int lane = tid & 31;
    const int row0 = blockIdx.x * 128;

    float* lv = (float*)(smc + OB_LV);
    int*   li = (int*)  (smc + OB_LI);

    // ---- prologue: async copies (A, B0, B1) ----
    {
        const char* srchi = (const char*)g_hb_hi + (size_t)row0*128;
        const char* srclo = (const char*)g_hb_lo + (size_t)row0*128;
        for (int i = tid; i < 1024; i += 256) {
            cp16(sb + OB_A + i*16,          srchi + i*16);
            cp16(sb + OB_A + 16384 + i*16,  srclo + i*16);
        }
        cp_commit();
        #pragma unroll
        for (int tt = 0; tt < 2; tt++) {
            const char* bhi = (const char*)g_hb_hi + (size_t)tt*16384;
            const char* blo = (const char*)g_hb_lo + (size_t)tt*16384;
            uint32_t dst = sb + OB_B + (uint32_t)tt*32768u;
            for (int i = tid; i < 1024; i += 256) {
                cp16(dst + i*16,          bhi + i*16);
                cp16(dst + 16384 + i*16,  blo + i*16);
            }
            if (tid < 32) cp16(sb + OB_HSQ + (uint32_t)tt*512u + tid*16,
                               (const char*)g_hsq + (size_t)tt*512 + tid*16);
            cp_commit();
        }
    }
    if (tid < 128) {
        #pragma unroll
        for (int p = 0; p < 17; p++) {
            lv[tid*17 + p] = 3.4e38f;
            li[tid*17 + p] = 0x7FFFFFFF;
        }
    }
    cp_wait<1>();          // A + B0 resident
    __syncthreads();

    // ---- preload A fragments (fixed across all tiles) ----
    uint32_t af[2][4][4];
    {
        const int m  = lane >> 3;
        const int rr = (w << 4) + ((m & 1) << 3) + (lane & 7);
        const int kb0 = (m >> 1) << 4;
        #pragma unroll
        for (int sp = 0; sp < 2; sp++) {
            uint32_t base = sb + OB_A + (uint32_t)sp*16384u;
            #pragma unroll
            for (int ks = 0; ks < 4; ks++) {
                uint32_t loc = (uint32_t)rr*128u + (uint32_t)(ks*32 + kb0);
                ldsm4(af[sp][ks][0], af[sp][ks][1], af[sp][ks][2], af[sp][ks][3],
                      base + sw128(loc));
            }
        }
    }

    const int q   = lane >> 2;            // row within m16 (and +8)
    const int s3  = lane & 3;             // column pair selector
    const int lr0 = (w << 4) + q;
    const int lr1 = lr0 + 8;
    float th0 = 3.4e38f, th1 = 3.4e38f;

    const int bm = lane >> 3;             // ldmatrix B address helper
    const int bn = lane & 7;

    for (int t = 0; t < 128; t++) {
        const uint32_t bbase = sb + OB_B + (uint32_t)(t & 1)*32768u;
        const char* hsqp = smc + OB_HSQ + (uint32_t)(t & 1)*512u;
        const int jb = t * 128;

        #pragma unroll 1
        for (int nb = 0; nb < 16; nb++) {
            // ---- B fragments: 2 splits x 4 k-steps via 4 ldmatrix.x4 ----
            uint32_t bh[8], bl[8];
            {
                uint32_t loc = (uint32_t)((nb*8 + bn)*128 + bm*16);
                ldsm4(bh[0], bh[1], bh[2], bh[3], bbase + sw128(loc));
                ldsm4(bh[4], bh[5], bh[6], bh[7], bbase + sw128(loc + 64u));
                uint32_t lb = bbase + 16384u;
                ldsm4(bl[0], bl[1], bl[2], bl[3], lb + sw128(loc));
                ldsm4(bl[4], bl[5], bl[6], bl[7], lb + sw128(loc + 64u));
            }
            // ---- 3 independent accumulator chains: hi*hi, hi*lo, lo*hi ----
            float h0 = 0.f, h1 = 0.f, h2 = 0.f, h3 = 0.f;
            float m0 = 0.f, m1 = 0.f, m2 = 0.f, m3 = 0.f;
            float g0 = 0.f, g1 = 0.f, g2 = 0.f, g3 = 0.f;
            #pragma unroll
            for (int ks = 0; ks < 4; ks++) {
                mma_bf16(h0, h1, h2, h3,
                         af[0][ks][0], af[0][ks][1], af[0][ks][2], af[0][ks][3],
                         bh[2*ks], bh[2*ks+1]);
                mma_bf16(m0, m1, m2, m3,
                         af[0][ks][0], af[0][ks][1], af[0][ks][2], af[0][ks][3],
                         bl[2*ks], bl[2*ks+1]);
                mma_bf16(g0, g1, g2, g3,
                         af[1][ks][0], af[1][ks][1], af[1][ks][2], af[1][ks][3],
                         bh[2*ks], bh[2*ks+1]);
            }
            float c0 = h0 + m0 + g0;
            float c1 = h1 + m1 + g1;
            float c2 = h2 + m2 + g2;
            float c3 = h3 + m3 + g3;

            // ---- epilogue: key = 0.5*sq_c - dot; threshold + rare insert ----
            float2 hs = *(const float2*)(hsqp + (nb*8 + 2*s3)*4);
            float k0 = hs.x - c0;
            float k1 = hs.y - c1;
            float k2 = hs.x - c2;
            float k3 = hs.y - c3;
            bool p0 = k0 < th0, p1 = k1 < th0, p2 = k2 < th1, p3 = k3 < th1;
            unsigned any = __ballot_sync(0xffffffffu, p0 | p1 | p2 | p3);
            if (any) {
                const int colb = jb + nb*8 + 2*s3;
                #pragma unroll
                for (int s = 0; s < 4; s++) {
                    __syncwarp();
                    if (s3 == s && (p0 | p1 | p2 | p3)) {
                        float* L0 = lv + lr0*17; int* I0 = li + lr0*17;
                        float t0 = L0[16];
                        if (k0 < t0) { ins17(L0, I0, k0, colb);   t0 = L0[16]; }
                        if (k1 < t0) { ins17(L0, I0, k1, colb+1); }
                        float* L1 = lv + lr1*17; int* I1 = li + lr1*17;
                        float t1 = L1[16];
                        if (k2 < t1) { ins17(L1, I1, k2, colb);   t1 = L1[16]; }
                        if (k3 < t1) { ins17(L1, I1, k3, colb+1); }
                    }
                }
                __syncwarp();
                th0 = lv[lr0*17 + 16];
                th1 = lv[lr1*17 + 16];
            }
        }

        __syncthreads();     // all warps done with buf[t&1] + lists stable
        if (t + 2 < 128) {
            const int tt = t + 2;
            const char* bhi = (const char*)g_hb_hi + (size_t)tt*16384;
            const char* blo = (const char*)g_hb_lo + (size_t)tt*16384;
            uint32_t dst = sb + OB_B + (uint32_t)(t & 1)*32768u;
            for (int i = tid; i < 1024; i += 256) {
                cp16(dst + i*16,          bhi + i*16);
                cp16(dst + 16384 + i*16,  blo + i*16);
            }
            if (tid < 32) cp16(sb + OB_HSQ + (uint32_t)(t & 1)*512u + tid*16,
                               (const char*)g_hsq + (size_t)tt*512 + tid*16);
            cp_commit();
            cp_wait<1>();    // tile t+1 resident
        } else {
            cp_wait<0>();
        }
        __syncthreads();
    }

    if (tid < 128) {
        #pragma unroll
        for (int p = 0; p < 17; p++)
            g_idx[(row0 + tid)*KK + p] = li[tid*17 + p];
    }
}

// ------------- GEMM A: depth-128 (MODE 0: msg gather, MODE 1: upd concat)
template<int MODE>
__global__ __launch_bounds__(256) void k_gemm_a(const float* __restrict__ W,
                                                const float* __restrict__ bias) {
    __shared__ float As[64][128];
    __shared__ float Ws[64][64];
    const int tid = threadIdx.x;
    const int e0  = blockIdx.x * 128;
    const int r0  = (tid >> 4) * 8;
    const int f0  = (tid & 15) * 4;
    ull acc[4][4];
    #pragma unroll
    for (int rp = 0; rp < 4; rp++)
        #pragma unroll
        for (int c = 0; c < 4; c++) acc[rp][c] = 0ull;

    for (int p = 0; p < 2; p++) {
        for (int t = tid; t < 1024; t += 256) {
            int f4 = t & 15, kk = t >> 4;
            *(float4*)&Ws[kk][f4<<2] =
                *(const float4*)(W + (size_t)((p<<6)+kk)*64 + (f4<<2));
        }
        for (int t = tid; t < 2048; t += 256) {
            int e = t & 127, k4 = t >> 7;
            int eg = e0 + e;
            const float* src;
            if (MODE == 0) {
                int i = eg & (Nn-1);
                int node = (p == 0) ? g_idx[i*KK + 1 + (eg >> 14)] : g_idx[i*KK];
                src = g_h + (size_t)node*64;
            } else {
                src = (p == 0 ? g_h : g_agg) + (size_t)eg*64;
            }
            float4 v = *(const float4*)(src + (k4<<2));
            As[(k4<<2)+0][e] = v.x; As[(k4<<2)+1][e] = v.y;
            As[(k4<<2)+2][e] = v.z; As[(k4<<2)+3][e] = v.w;
        }
        __syncthreads();
        #pragma unroll 4
        for (int k = 0; k < 64; k++) {
            ulonglong2 a01 = *(const ulonglong2*)(&As[k][r0]);
            ulonglong2 a23 = *(const ulonglong2*)(&As[k][r0+4]);
            float4 b = *(const float4*)(&Ws[k][f0]);
            ull ar[4] = { a01.x, a01.y, a23.x, a23.y };
            ull bd[4] = { dup2(b.x), dup2(b.y), dup2(b.z), dup2(b.w) };
            #pragma unroll
            for (int rp = 0; rp < 4; rp++)
                #pragma unroll
                for (int c = 0; c < 4; c++)
                    acc[rp][c] = ff2(ar[rp], bd[c], acc[rp][c]);
        }
        __syncthreads();
    }

    float* out = (MODE == 0) ? g_y1 : g_u1;
    float4 bv = *(const float4*)(bias + f0);
    #pragma unroll
    for (int rp = 0; rp < 4; rp++) {
        float2 u0 = up2(acc[rp][0]), u1 = up2(acc[rp][1]);
        float2 u2 = up2(acc[rp][2]), u3 = up2(acc[rp][3]);
        int ea = e0 + r0 + 2*rp;
        *(float4*)(out + (size_t)ea*64 + f0) =
            make_float4(u0.x + bv.x, u1.x + bv.y, u2.x + bv.z, u3.x + bv.w);
        *(float4*)(out + (size_t)(ea+1)*64 + f0) =
            make_float4(u0.y + bv.x, u1.y + bv.y, u2.y + bv.z, u3.y + bv.w);
    }
}

// ------------- GEMM B: depth-64 with fused BN-affine + ReLU on input ----
template<int MODE>
__global__ __launch_bounds__(256) void k_gemm_b(const float* __restrict__ W,
                                                const float* __restrict__ bias) {
    __shared__ float As[64][128];
    __shared__ float Ws[64][64];
    const int tid = threadIdx.x;
    const int e0  = blockIdx.x * 128;
    const int r0  = (tid >> 4) * 8;
    const int f0  = (tid & 15) * 4;

    const float* in = (MODE == 0) ? g_y1 : g_u1;

    for (int t = tid; t < 1024; t += 256) {
        int f4 = t & 15, kk = t >> 4;
        *(float4*)&Ws[kk][f4<<2] = *(const float4*)(W + (size_t)kk*64 + (f4<<2));
    }
    for (int t = tid; t < 2048; t += 256) {
        int e = t & 127, k4 = t >> 7;
        int eg = e0 + e;
        float4 v  = *(const float4*)(in + (size_t)eg*64 + (k4<<2));
        float4 sc = *(const float4*)(g_scale + (k4<<2));
        float4 sh = *(const float4*)(g_shift + (k4<<2));
        As[(k4<<2)+0][e] = fmaxf(fmaf(v.x, sc.x, sh.x), 0.f);
        As[(k4<<2)+1][e] = fmaxf(fmaf(v.y, sc.y, sh.y), 0.f);
        As[(k4<<2)+2][e] = fmaxf(fmaf(v.z, sc.z, sh.z), 0.f);
        As[(k4<<2)+3][e] = fmaxf(fmaf(v.w, sc.w, sh.w), 0.f);
    }
    __syncthreads();

    ull acc[4][4];
    #pragma unroll
    for (int rp = 0; rp < 4; rp++)
        #pragma unroll
        for (int c = 0; c < 4; c++) acc[rp][c] = 0ull;

    #pragma unroll 4
    for (int k = 0; k < 64; k++) {
        ulonglong2 a01 = *(const ulonglong2*)(&As[k][r0]);
        ulonglong2 a23 = *(const ulonglong2*)(&As[k][r0+4]);
        float4 b = *(const float4*)(&Ws[k][f0]);
        ull ar[4] = { a01.x, a01.y, a23.x, a23.y };
        ull bd[4] = { dup2(b.x), dup2(b.y), dup2(b.z), dup2(b.w) };
        #pragma unroll
        for (int rp = 0; rp < 4; rp++)
            #pragma unroll
            for (int c = 0; c < 4; c++)
                acc[rp][c] = ff2(ar[rp], bd[c], acc[rp][c]);
    }

    float* out = (MODE == 0) ? g_y2 : g_u2;
    float4 bv = *(const float4*)(bias + f0);
    #pragma unroll
    for (int rp = 0; rp < 4; rp++) {
        float2 u0 = up2(acc[rp][0]), u1 = up2(acc[rp][1]);
        float2 u2 = up2(acc[rp][2]), u3 = up2(acc[rp][3]);
        int ea = e0 + r0 + 2*rp;
        *(float4*)(out + (size_t)ea*64 + f0) =
            make_float4(u0.x + bv.x, u1.x + bv.y, u2.x + bv.z, u3.x + bv.w);
        *(float4*)(out + (size_t)(ea+1)*64 + f0) =
            make_float4(u0.y + bv.x, u1.y + bv.y, u2.y + bv.z, u3.y + bv.w);
    }
}

// ---------------- batch statistics (deterministic two-pass) ------------
__device__ __forceinline__ const float* stat_src(int sel) {
    switch (sel) {
        case 0: return g_y1;
        case 1: return g_y2;
        case 2: return g_u1;
        case 3: return g_u2;
        default: return g_h;
    }
}

__global__ void k_stats(int sel, int M, int P) {
    const float* __restrict__ x = stat_src(sel);
    const int t = threadIdx.x;
    float s = 0.f, s2 = 0.f;
    const size_t total = (size_t)M * 64;
    for (size_t idx = (size_t)blockIdx.x*256 + t; idx < total; idx += (size_t)P*256) {
        float v = x[idx];
        s += v; s2 = fmaf(v, v, s2);
    }
    __shared__ float sh[256], sh2[256];
    sh[t] = s; sh2[t] = s2;
    __syncthreads();
    if (t < 64) {
        s  = sh[t]  + sh[t+64]  + sh[t+128]  + sh[t+192];
        s2 = sh2[t] + sh2[t+64] + sh2[t+128] + sh2[t+192];
        g_part[(size_t)blockIdx.x*128 + t]      = s;
        g_part[(size_t)blockIdx.x*128 + 64 + t] = s2;
    }
}

__global__ void k_stats_fin(int M, int P,
                            const float* __restrict__ g,
                            const float* __restrict__ be) {
    const int f = threadIdx.x;
    float s = 0.f, s2 = 0.f;
    for (int p = 0; p < P; p++) {
        s  += g_part[(size_t)p*128 + f];
        s2 += g_part[(size_t)p*128 + 64 + f];
    }
    const float inv  = 1.f / (float)M;
    const float mean = s * inv;
    const float var  = fmaf(-mean, mean, s2 * inv);
    const float sc   = g[f] * rsqrtf(var + 1e-5f);
    g_scale[f] = sc;
    g_shift[f] = fmaf(-mean, sc, be[f]);
}

// ---------------- zero, scatter, residual ----------------
__global__ void k_zero_agg() {
    int i = blockIdx.x*blockDim.x + threadIdx.x;
    g_agg[i] = 0.f;
}

__global__ void k_scatter() {
    const int gid = blockIdx.x*256 + threadIdx.x;
    const int q = gid & 15;
    const int e = gid >> 4;
    const int i = e & (Nn-1);
    const int to = g_idx[i*KK + 1 + (e >> 14)];
    const int f = q << 2;
    float4 v  = *(const float4*)(g_y2 + (size_t)e*64 + f);
    float4 sc = *(const float4*)(g_scale + f);
    float4 sh = *(const float4*)(g_shift + f);
    float* dst = g_agg + (size_t)to*64 + f;
    atomicAdd(dst+0, fmaxf(fmaf(v.x, sc.x, sh.x), 0.f));
    atomicAdd(dst+1, fmaxf(fmaf(v.y, sc.y, sh.y), 0.f));
    atomicAdd(dst+2, fmaxf(fmaf(v.z, sc.z, sh.z), 0.f));
    atomicAdd(dst+3, fmaxf(fmaf(v.w, sc.w, sh.w), 0.f));
}

__global__ void k_resid() {
    const int gid = blockIdx.x*blockDim.x + threadIdx.x;
    const int f = gid & 63;
    const float v = g_u2[gid];
    g_h[gid] += fmaxf(fmaf(v, g_scale[f], g_shift[f]), 0.f);
}

// ---------------- final pool + prediction ----------------
__global__ void k_fin(const float* __restrict__ pW,
                      const float* __restrict__ pb,
                      float* __restrict__ out, int P) {
    const int f = threadIdx.x;
    float s = 0.f;
    for (int p = 0; p < P; p++) s += g_part[(size_t)p*128 + f];
    float v = (s / (float)Nn) * pW[f];
    __shared__ float red[64];
    red[f] = v;
    __syncthreads();
    if (f < 32) {
        float x = red[f] + red[f+32];
        #pragma unroll
        for (int o = 16; o > 0; o >>= 1) x += __shfl_down_sync(0xffffffffu, x, o);
        if (f == 0) out[0] = x + pb[0];
    }
}

// ---------------- host driver ----------------
extern "C" void kernel_launch(void* const* d_in, const int* in_sizes, int n_in,
                              void* d_out, int out_size) {
    const float* pos    = (const float*)d_in[0];
    const float* linW   = (const float*)d_in[1];
    const float* linb   = (const float*)d_in[2];
    const float* predW  = (const float*)d_in[3];
    const float* predb  = (const float*)d_in[4];
    const float* msgW1  = (const float*)d_in[5];
    const float* msgb1  = (const float*)d_in[6];
    const float* msgg1  = (const float*)d_in[7];
    const float* msgbe1 = (const float*)d_in[8];
    const float* msgW2  = (const float*)d_in[9];
    const float* msgb2  = (const float*)d_in[10];
    const float* msgg2  = (const float*)d_in[11];
    const float* msgbe2 = (const float*)d_in[12];
    const float* updW1  = (const float*)d_in[13];
    const float* updb1  = (const float*)d_in[14];
    const float* updg1  = (const float*)d_in[15];
    const float* updbe1 = (const float*)d_in[16];
    const float* updW2  = (const float*)d_in[17];
    const float* updb2  = (const float*)d_in[18];
    const float* updg2  = (const float*)d_in[19];
    const float* updbe2 = (const float*)d_in[20];
    float* out = (float*)d_out;

    static int smem_set = 0;
    if (!smem_set) {
        cudaFuncSetAttribute(k_d2topk, cudaFuncAttributeMaxDynamicSharedMemorySize,
                             SMEM_D2);
        smem_set = 1;
    }

    k_lin_in<<<Nn, 64>>>(pos, linW, linb);

    for (int l = 0; l < Ll; l++) {
        // ---- KNN: bf16 split + mma.sync d2 + top-17 ----
        k_split<<<Nn/8, 256>>>();
        k_d2topk<<<Nn/128, 256, SMEM_D2>>>();

        // ---- message MLP over E edges ----
        k_gemm_a<0><<<Ee/128, 256>>>(msgW1 + (size_t)l*128*64, msgb1 + l*64);
        k_stats<<<2048, 256>>>(0, Ee, 2048);
        k_stats_fin<<<1, 64>>>(Ee, 2048, msgg1 + l*64, msgbe1 + l*64);
        k_gemm_b<0><<<Ee/128, 256>>>(msgW2 + (size_t)l*64*64, msgb2 + l*64);
        k_stats<<<2048, 256>>>(1, Ee, 2048);
        k_stats_fin<<<1, 64>>>(Ee, 2048, msgg2 + l*64, msgbe2 + l*64);

        // ---- aggregate ----
        k_zero_agg<<<Nn*64/256, 256>>>();
        k_scatter<<<Ee*16/256, 256>>>();

        // ---- update MLP + residual ----
        k_gemm_a<1><<<Nn/128, 256>>>(updW1 + (size_t)l*128*64, updb1 + l*64);
        k_stats<<<64, 256>>>(2, Nn, 64);
        k_stats_fin<<<1, 64>>>(Nn, 64, updg1 + l*64, updbe1 + l*64);
        k_gemm_b<1><<<Nn/128, 256>>>(updW2 + (size_t)l*64*64, updb2 + l*64);
        k_stats<<<64, 256>>>(3, Nn, 64);
        k_stats_fin<<<1, 64>>>(Nn, 64, updg2 + l*64, updbe2 + l*64);
        k_resid<<<Nn*64/256, 256>>>();
    }

    k_stats<<<64, 256>>>(4, Nn, 64);
    k_fin<<<1, 64>>>(predW, predb, out, 64);
}